// round 1
// baseline (speedup 1.0000x reference)
#include <cuda_runtime.h>
#include <math_constants.h>

// Sparsemax along last dim. Input: (64, 1024, 512) fp32 -> 65536 rows x 512.
// One warp per row. 512 elems = 16 regs/lane via 4x float4 coalesced loads.
// tau found by Newton on f(tau) = sum(relu(z - tau)) - 1  (piecewise linear,
// convex, decreasing). Start tau0 = zmax - 1 (f >= 0); Newton converges
// monotonically and exactly (finite segments). Output = relu(z - tau).

#define N_COLS 512
#define VEC_PER_LANE 4   // 4 x float4 = 16 floats per lane

__global__ __launch_bounds__(256) void sparsemax_kernel(
    const float* __restrict__ x, float* __restrict__ out, int rows)
{
    const int warps_per_block = blockDim.x >> 5;
    const int row = blockIdx.x * warps_per_block + (threadIdx.x >> 5);
    if (row >= rows) return;
    const int lane = threadIdx.x & 31;

    const float4* __restrict__ in  = reinterpret_cast<const float4*>(x   + (size_t)row * N_COLS);
    float4*       __restrict__ op  = reinterpret_cast<float4*>(      out + (size_t)row * N_COLS);

    float z[16];
    float m = -CUDART_INF_F;

    #pragma unroll
    for (int i = 0; i < VEC_PER_LANE; i++) {
        float4 v = in[i * 32 + lane];
        z[i*4+0] = v.x; z[i*4+1] = v.y; z[i*4+2] = v.z; z[i*4+3] = v.w;
        m = fmaxf(m, fmaxf(fmaxf(v.x, v.y), fmaxf(v.z, v.w)));
    }

    // warp max
    #pragma unroll
    for (int o = 16; o; o >>= 1)
        m = fmaxf(m, __shfl_xor_sync(0xffffffffu, m, o));

    #pragma unroll
    for (int i = 0; i < 16; i++) z[i] -= m;   // zmax = 0 now

    // Newton: tau0 = zmax - 1 = -1. f(tau) = sum(relu(z - tau)) - 1.
    float tau = -1.0f;
    for (int it = 0; it < 64; it++) {
        float s = 0.0f, k = 0.0f;
        #pragma unroll
        for (int i = 0; i < 16; i++) {
            float t = z[i] - tau;
            if (t > 0.0f) { s += t; k += 1.0f; }
        }
        #pragma unroll
        for (int o = 16; o; o >>= 1) {
            s += __shfl_xor_sync(0xffffffffu, s, o);
            k += __shfl_xor_sync(0xffffffffu, k, o);
        }
        float tn = tau + (s - 1.0f) / k;   // k >= 1 while f >= 0
        if (tn == tau) break;              // exact fixed point (warp-uniform)
        tau = tn;
    }

    #pragma unroll
    for (int i = 0; i < VEC_PER_LANE; i++) {
        float4 v;
        v.x = fmaxf(z[i*4+0] - tau, 0.0f);
        v.y = fmaxf(z[i*4+1] - tau, 0.0f);
        v.z = fmaxf(z[i*4+2] - tau, 0.0f);
        v.w = fmaxf(z[i*4+3] - tau, 0.0f);
        op[i * 32 + lane] = v;
    }
}

extern "C" void kernel_launch(void* const* d_in, const int* in_sizes, int n_in,
                              void* d_out, int out_size)
{
    const float* x = (const float*)d_in[0];
    float* out = (float*)d_out;
    const int n = in_sizes[0];
    const int rows = n / N_COLS;

    const int threads = 256;                      // 8 warps = 8 rows per block
    const int rows_per_block = threads / 32;
    const int blocks = (rows + rows_per_block - 1) / rows_per_block;
    sparsemax_kernel<<<blocks, threads>>>(x, out, rows);
}

// round 2
// speedup vs baseline: 1.3171x; 1.3171x over previous
#include <cuda_runtime.h>
#include <math_constants.h>

// Sparsemax along last dim. Input: (64, 1024, 512) fp32 -> 65536 rows x 512.
// One warp per row, 16 fp32/lane in registers (4x float4).
//
// Key fact: tau >= z_max - 1, so only elements with x > max - 1 can be in the
// support (~6/row for gaussian data). Compact those into a per-warp shared
// buffer once, then run Newton on the tiny candidate set:
//   f(tau) = sum(relu(x - tau)) - 1, convex piecewise-linear decreasing;
//   tau' = tau + (s-1)/k converges monotonically from tau0 = max - 1.
// Fast path: cnt <= 32 -> one candidate per lane, k via ballot+popc.
// Slow path (degenerate rows, e.g. all-equal): loop over shared buffer.

#define N_COLS 512
#define WARPS_PER_BLOCK 8

__global__ __launch_bounds__(256) void sparsemax_kernel(
    const float* __restrict__ x, float* __restrict__ out, int rows)
{
    __shared__ float cand[WARPS_PER_BLOCK][N_COLS];
    __shared__ int   cnt_s[WARPS_PER_BLOCK];

    const int wib  = threadIdx.x >> 5;
    const int row  = blockIdx.x * WARPS_PER_BLOCK + wib;
    if (row >= rows) return;
    const int lane = threadIdx.x & 31;

    const float4* __restrict__ in = reinterpret_cast<const float4*>(x   + (size_t)row * N_COLS);
    float4*       __restrict__ op = reinterpret_cast<float4*>(      out + (size_t)row * N_COLS);

    float z[16];
    float m = -CUDART_INF_F;
    #pragma unroll
    for (int i = 0; i < 4; i++) {
        float4 v = in[i * 32 + lane];
        z[i*4+0] = v.x; z[i*4+1] = v.y; z[i*4+2] = v.z; z[i*4+3] = v.w;
        m = fmaxf(m, fmaxf(fmaxf(v.x, v.y), fmaxf(v.z, v.w)));
    }
    #pragma unroll
    for (int o = 16; o; o >>= 1)
        m = fmaxf(m, __shfl_xor_sync(0xffffffffu, m, o));

    const float thr = m - 1.0f;        // tau >= thr always

    if (lane == 0) cnt_s[wib] = 0;
    __syncwarp();

    // Compact candidates (x > thr) into shared. Order irrelevant.
    #pragma unroll
    for (int i = 0; i < 16; i++) {
        if (z[i] > thr) {
            int p = atomicAdd(&cnt_s[wib], 1);
            cand[wib][p] = z[i];
        }
    }
    __syncwarp();
    const int cnt = cnt_s[wib];

    float tau = thr;
    if (cnt <= 32) {
        // one candidate per lane
        float c = (lane < cnt) ? cand[wib][lane] : -CUDART_INF_F;
        #pragma unroll 1
        for (int it = 0; it < 32; it++) {
            float t = c - tau;
            bool  p = t > 0.0f;
            unsigned b = __ballot_sync(0xffffffffu, p);
            float s = p ? t : 0.0f;
            #pragma unroll
            for (int o = 16; o; o >>= 1)
                s += __shfl_xor_sync(0xffffffffu, s, o);
            int k = __popc(b);
            if (k == 0) break;
            float tn = tau + (s - 1.0f) / (float)k;
            if (!(tn > tau)) break;    // converged (monotone from below)
            tau = tn;
        }
    } else {
        // degenerate rows (many near-max elements)
        #pragma unroll 1
        for (int it = 0; it < 64; it++) {
            float s = 0.0f, k = 0.0f;
            for (int j = lane; j < cnt; j += 32) {
                float t = cand[wib][j] - tau;
                if (t > 0.0f) { s += t; k += 1.0f; }
            }
            #pragma unroll
            for (int o = 16; o; o >>= 1) {
                s += __shfl_xor_sync(0xffffffffu, s, o);
                k += __shfl_xor_sync(0xffffffffu, k, o);
            }
            if (k == 0.0f) break;
            float tn = tau + (s - 1.0f) / k;
            if (!(tn > tau)) break;
            tau = tn;
        }
    }

    #pragma unroll
    for (int i = 0; i < 4; i++) {
        float4 v;
        v.x = fmaxf(z[i*4+0] - tau, 0.0f);
        v.y = fmaxf(z[i*4+1] - tau, 0.0f);
        v.z = fmaxf(z[i*4+2] - tau, 0.0f);
        v.w = fmaxf(z[i*4+3] - tau, 0.0f);
        op[i * 32 + lane] = v;
    }
}

extern "C" void kernel_launch(void* const* d_in, const int* in_sizes, int n_in,
                              void* d_out, int out_size)
{
    const float* x = (const float*)d_in[0];
    float* out = (float*)d_out;
    const int n = in_sizes[0];
    const int rows = n / N_COLS;

    const int threads = 32 * WARPS_PER_BLOCK;
    const int blocks = (rows + WARPS_PER_BLOCK - 1) / WARPS_PER_BLOCK;
    sparsemax_kernel<<<blocks, threads>>>(x, out, rows);
}

// round 4
// speedup vs baseline: 1.3661x; 1.0372x over previous
#include <cuda_runtime.h>
#include <math_constants.h>

// Sparsemax along last dim. Input: (64, 1024, 512) fp32 -> 65536 rows x 512.
// One warp per row, 16 fp32/lane in registers (4x float4).
// tau >= max-1 => candidates are x > max-1 (~6/row gaussian). Compact into a
// 32-entry per-warp shared buffer, Newton on f(tau)=sum(relu(x-tau))-1 from
// tau0=max-1 (monotone from below, exact on piecewise-linear f).
// sm_103: integer redux.sync only -> max via monotone uint key; float sums
// via shuffle butterfly; counts via ballot+popc.

#define N_COLS 512
#define WARPS_PER_BLOCK 8

// monotone mapping float -> uint (preserves order for all finite floats)
__device__ __forceinline__ unsigned fkey(float x) {
    unsigned b = __float_as_uint(x);
    return b ^ (unsigned)(((int)b >> 31) | 0x80000000);
}
__device__ __forceinline__ float funkey(unsigned k) {
    unsigned m = (unsigned)((~((int)k >> 31)) | 0x80000000);
    return __uint_as_float(k ^ m);
}

__device__ __forceinline__ float warp_sum_f32(float v) {
    #pragma unroll
    for (int o = 16; o; o >>= 1)
        v += __shfl_xor_sync(0xffffffffu, v, o);
    return v;
}

__global__ __launch_bounds__(256) void sparsemax_kernel(
    const float* __restrict__ x, float* __restrict__ out, int rows)
{
    __shared__ float cand[WARPS_PER_BLOCK][32];
    __shared__ int   cnt_s[WARPS_PER_BLOCK];

    const int wib  = threadIdx.x >> 5;
    const int row  = blockIdx.x * WARPS_PER_BLOCK + wib;
    if (row >= rows) return;
    const int lane = threadIdx.x & 31;

    const float4* __restrict__ in = reinterpret_cast<const float4*>(x   + (size_t)row * N_COLS);
    float4*       __restrict__ op = reinterpret_cast<float4*>(      out + (size_t)row * N_COLS);

    float z[16];
    unsigned km = 0;
    #pragma unroll
    for (int i = 0; i < 4; i++) {
        float4 v = in[i * 32 + lane];
        z[i*4+0] = v.x; z[i*4+1] = v.y; z[i*4+2] = v.z; z[i*4+3] = v.w;
        float mm = fmaxf(fmaxf(v.x, v.y), fmaxf(v.z, v.w));
        unsigned k = fkey(mm);
        km = k > km ? k : km;
    }
    km = __reduce_max_sync(0xffffffffu, km);     // single-instr warp max
    const float m   = funkey(km);
    const float thr = m - 1.0f;                  // tau >= thr always

    if (lane == 0) cnt_s[wib] = 0;
    __syncwarp();

    // Compact candidates (z > thr) into shared (cap 32); accumulate
    // s0 = sum(z - thr) for a free first Newton step.
    float s0 = 0.0f;
    #pragma unroll
    for (int i = 0; i < 16; i++) {
        if (z[i] > thr) {
            s0 += z[i] - thr;
            int p = atomicAdd(&cnt_s[wib], 1);
            if (p < 32) cand[wib][p] = z[i];
        }
    }
    s0 = warp_sum_f32(s0);                       // s0 >= 1 (max contributes 1)
    __syncwarp();
    const int cnt = cnt_s[wib];

    // First Newton update: tau1 = thr + (s0-1)/cnt (monotone from below)
    float tau = thr + __fdividef(s0 - 1.0f, (float)cnt);

    if (cnt <= 32) {
        // one candidate per lane
        float c = (lane < cnt) ? cand[wib][lane] : -CUDART_INF_F;
        #pragma unroll 1
        for (int it = 0; it < 32; it++) {
            float t = c - tau;
            unsigned b = __ballot_sync(0xffffffffu, t > 0.0f);
            float s = warp_sum_f32(fmaxf(t, 0.0f));
            int   k = __popc(b);
            if (k == 0) break;
            float tn = tau + __fdividef(s - 1.0f, (float)k);
            if (!(tn > tau)) break;              // converged
            tau = tn;
        }
    } else {
        // degenerate rows (many near-max values): scan registers directly
        #pragma unroll 1
        for (int it = 0; it < 64; it++) {
            float s = 0.0f; int k = 0;
            #pragma unroll
            for (int i = 0; i < 16; i++) {
                float t = z[i] - tau;
                if (t > 0.0f) { s += t; k++; }
            }
            s = warp_sum_f32(s);
            k = __reduce_add_sync(0xffffffffu, k);
            if (k == 0) break;
            float tn = tau + __fdividef(s - 1.0f, (float)k);
            if (!(tn > tau)) break;
            tau = tn;
        }
    }

    #pragma unroll
    for (int i = 0; i < 4; i++) {
        float4 v;
        v.x = fmaxf(z[i*4+0] - tau, 0.0f);
        v.y = fmaxf(z[i*4+1] - tau, 0.0f);
        v.z = fmaxf(z[i*4+2] - tau, 0.0f);
        v.w = fmaxf(z[i*4+3] - tau, 0.0f);
        __stcs(&op[i * 32 + lane], v);
    }
}

extern "C" void kernel_launch(void* const* d_in, const int* in_sizes, int n_in,
                              void* d_out, int out_size)
{
    const float* x = (const float*)d_in[0];
    float* out = (float*)d_out;
    const int n = in_sizes[0];
    const int rows = n / N_COLS;

    const int threads = 32 * WARPS_PER_BLOCK;
    const int blocks = (rows + WARPS_PER_BLOCK - 1) / WARPS_PER_BLOCK;
    sparsemax_kernel<<<blocks, threads>>>(x, out, rows);
}